// round 14
// baseline (speedup 1.0000x reference)
#include <cuda_runtime.h>
#include <cuda_fp16.h>
#include <stdint.h>
#include <math.h>

// Problem constants
#define BATCH 4
#define SEQ   2048
#define EMB   1024
#define HEAD  64
#define NROWS (BATCH * SEQ)   // 8192
#define SPLITK 4
#define QSC   0.180336881f    // (1/8) * log2(e) : softmax in exp2 domain

// ---------------- scratch ----------------
__device__ __half g_xh[NROWS * EMB];           // fp16-rounded x
__device__ __half g_qh[NROWS * HEAD];          // fp16, pre-scaled by QSC
__device__ __half g_kh[NROWS * HEAD];          // fp16
__device__ __half g_vth[NROWS * HEAD];         // fp16, per-64-tile transposed [tile][head][key]
__device__ float  g_om[SPLITK * NROWS * HEAD];
__device__ float  g_m [SPLITK * NROWS];        // log2-domain row maxima
__device__ float  g_l [SPLITK * NROWS];
__device__ float  g_mu[NROWS];
__device__ float  g_rs[NROWS];
__device__ __half g_wh[192 * EMB];
__device__ float  g_wsum [192];
__device__ float  g_wbeta[192];
__device__ int    g_cnt[BATCH * 32];

__device__ __forceinline__ uint32_t pack_h2(float lo, float hi) {
    __half2 h = __floats2half2_rn(lo, hi);
    return *reinterpret_cast<uint32_t*>(&h);
}

__device__ __forceinline__ float ex2(float x) {
    float r;
    asm("ex2.approx.ftz.f32 %0, %1;" : "=f"(r) : "f"(x));
    return r;
}

__device__ __forceinline__ void mma_f16(float* d, const uint32_t* a,
                                        uint32_t b0, uint32_t b1) {
    asm volatile(
        "mma.sync.aligned.m16n8k16.row.col.f32.f16.f16.f32 "
        "{%0,%1,%2,%3}, {%4,%5,%6,%7}, {%8,%9}, {%0,%1,%2,%3};"
        : "+f"(d[0]), "+f"(d[1]), "+f"(d[2]), "+f"(d[3])
        : "r"(a[0]), "r"(a[1]), "r"(a[2]), "r"(a[3]), "r"(b0), "r"(b1));
}

__device__ __forceinline__ void ldsm_x4(uint32_t& r0, uint32_t& r1,
                                        uint32_t& r2, uint32_t& r3, uint32_t addr) {
    asm volatile("ldmatrix.sync.aligned.m8n8.x4.shared.b16 {%0,%1,%2,%3}, [%4];"
                 : "=r"(r0), "=r"(r1), "=r"(r2), "=r"(r3) : "r"(addr));
}

__device__ __forceinline__ uint32_t smem_u32(const void* p) {
    return (uint32_t)__cvta_generic_to_shared(p);
}

#define CP_ASYNC16(dst_u32, src_ptr) \
    asm volatile("cp.async.cg.shared.global [%0], [%1], 16;" \
                 :: "r"(dst_u32), "l"(src_ptr))
#define CP_COMMIT() asm volatile("cp.async.commit_group;")
#define CP_WAIT(N)  asm volatile("cp.async.wait_group %0;" :: "n"(N))

// ================= Kernel 0: prep (x->fp16 + LN stats + weight prep) =========
// (R12 layout: unit-stride float4 loads, uint2 stores — measured best)
__global__ void __launch_bounds__(256)
prep_kernel(const float* __restrict__ x,
            const float* __restrict__ gamma,
            const float* __restrict__ beta,
            const float* __restrict__ Wq,
            const float* __restrict__ Wk,
            const float* __restrict__ Wv)
{
    const int tid  = threadIdx.x;
    const int warp = tid >> 5;
    const int lane = tid & 31;

    if (blockIdx.x < NROWS / 8) {
        const int r = blockIdx.x * 8 + warp;
        const float4* xr = (const float4*)(x + (size_t)r * EMB);
        __half* xh = g_xh + (size_t)r * EMB;
        float sum = 0.f, sq = 0.f;
        #pragma unroll
        for (int t = 0; t < 8; t++) {
            const int i4 = lane + 32 * t;
            float4 v = xr[i4];
            const float f0 = __half2float(__float2half_rn(v.x));
            const float f1 = __half2float(__float2half_rn(v.y));
            const float f2 = __half2float(__float2half_rn(v.z));
            const float f3 = __half2float(__float2half_rn(v.w));
            uint2 st;
            st.x = pack_h2(f0, f1);
            st.y = pack_h2(f2, f3);
            *reinterpret_cast<uint2*>(xh + i4 * 4) = st;
            sum += f0 + f1 + f2 + f3;
            sq  += f0*f0 + f1*f1 + f2*f2 + f3*f3;
        }
        #pragma unroll
        for (int off = 16; off; off >>= 1) {
            sum += __shfl_xor_sync(0xffffffffu, sum, off);
            sq  += __shfl_xor_sync(0xffffffffu, sq,  off);
        }
        if (lane == 0) {
            const float inv = 1.0f / (float)EMB;
            const float mu = sum * inv;
            const float var = sq * inv - mu * mu;
            g_mu[r] = mu;
            g_rs[r] = rsqrtf(var + 1e-5f);
        }
    } else {
        __shared__ float red[16];
        const int c = blockIdx.x - NROWS / 8;
        const float* Wr = (c < 64)  ? (Wq + (size_t)c * EMB)
                        : (c < 128) ? (Wk + (size_t)(c - 64) * EMB)
                                    : (Wv + (size_t)(c - 128) * EMB);
        float s_w = 0.f, s_b = 0.f;
        {
            float4 w = *(const float4*)(Wr + tid * 4);
            float4 g = *(const float4*)(gamma + tid * 4);
            float4 b = *(const float4*)(beta  + tid * 4);
            __half h0 = __float2half_rn(w.x * g.x);
            __half h1 = __float2half_rn(w.y * g.y);
            __half h2 = __float2half_rn(w.z * g.z);
            __half h3 = __float2half_rn(w.w * g.w);
            __half2 p0 = __halves2half2(h0, h1);
            __half2 p1 = __halves2half2(h2, h3);
            uint2 st;
            st.x = *reinterpret_cast<uint32_t*>(&p0);
            st.y = *reinterpret_cast<uint32_t*>(&p1);
            *reinterpret_cast<uint2*>(g_wh + (size_t)c * EMB + tid * 4) = st;
            s_w += __half2float(h0) + __half2float(h1) + __half2float(h2) + __half2float(h3);
            s_b += w.x*b.x + w.y*b.y + w.z*b.z + w.w*b.w;
        }
        #pragma unroll
        for (int off = 16; off; off >>= 1) {
            s_w += __shfl_xor_sync(0xffffffffu, s_w, off);
            s_b += __shfl_xor_sync(0xffffffffu, s_b, off);
        }
        if (lane == 0) { red[warp] = s_w; red[warp + 8] = s_b; }
        __syncthreads();
        if (tid == 0) {
            float aw = 0.f, ab = 0.f;
            #pragma unroll
            for (int i = 0; i < 8; i++) { aw += red[i]; ab += red[i + 8]; }
            g_wsum[c] = aw; g_wbeta[c] = ab;
        }
    }
}

// ================= Kernel 1: QKV GEMM (fp16 mma + ldmatrix, 3-stage) =========
#define K1_KC 64
#define ASTR2 72     // fp16 halves; 144B row stride -> conflict-free ldmatrix
#define BSTR2 72
#define K1_STAGE ((64*ASTR2 + 96*BSTR2) * 2)
#define K1_SMEM (3 * K1_STAGE)

__global__ void __launch_bounds__(256, 3)
qkv_gemm_kernel()
{
    extern __shared__ char sm1[];

    const int tid  = threadIdx.x;
    const int warp = tid >> 5;
    const int lane = tid & 31;
    const int rowBase = (blockIdx.x >> 1) * 64;
    const int nbase   = (blockIdx.x & 1) * 96;

    const uint32_t a_u = smem_u32(sm1);                       // A: [stage][64][72]
    const uint32_t b_u = a_u + 64 * ASTR2 * 2;                // B: [stage][96][72]

    const int wm  = warp >> 1;
    const int wn  = warp & 1;

    const int mi = lane >> 3, mrow = lane & 7;
    const int aoff = ((wm * 16 + (mi & 1) * 8 + mrow) * ASTR2 + (mi >> 1) * 8) * 2;
    const int boff = (((mi >> 1) * 8 + mrow) * BSTR2 + (mi & 1) * 8) * 2;

    auto stage = [&](int ch, int slot) {
        const int k0 = ch * K1_KC;
        const uint32_t au = a_u + slot * K1_STAGE;
        const uint32_t bu = b_u + slot * K1_STAGE;
        #pragma unroll
        for (int i = 0; i < 2; i++) {
            const int idx = tid + 256 * i;
            const int row = idx >> 3, c8 = idx & 7;
            CP_ASYNC16(au + (row * ASTR2 + c8 * 8) * 2,
                       g_xh + (size_t)(rowBase + row) * EMB + k0 + c8 * 8);
        }
        #pragma unroll
        for (int i = 0; i < 3; i++) {
            const int idx = tid + 256 * i;
            const int c = idx >> 3, c8 = idx & 7;
            CP_ASYNC16(bu + (c * BSTR2 + c8 * 8) * 2,
                       g_wh + (size_t)(nbase + c) * EMB + k0 + c8 * 8);
        }
        CP_COMMIT();
    };

    stage(0, 0);
    stage(1, 1);

    float acc[6][4];
    #pragma unroll
    for (int i = 0; i < 6; i++)
        #pragma unroll
        for (int j = 0; j < 4; j++) acc[i][j] = 0.f;

    for (int ch = 0; ch < EMB / K1_KC; ch++) {
        if (ch + 1 < EMB / K1_KC) { CP_WAIT(1); } else { CP_WAIT(0); }
        __syncthreads();
        if (ch + 2 < EMB / K1_KC) {
            int slot = ch + 2; slot -= (slot / 3) * 3;
            stage(ch + 2, slot);
        }

        int cslot = ch; cslot -= (cslot / 3) * 3;
        const uint32_t Ab_u = a_u + cslot * K1_STAGE;
        const uint32_t Bb_u = b_u + cslot * K1_STAGE;

        #pragma unroll
        for (int k16 = 0; k16 < 4; k16++) {
            uint32_t a[4];
            ldsm_x4(a[0], a[1], a[2], a[3], Ab_u + (k16 * 16) * 2 + aoff);
            #pragma unroll
            for (int tp = 0; tp < 3; tp++) {
                uint32_t b00, b01, b10, b11;
                ldsm_x4(b00, b01, b10, b11,
                        Bb_u + ((wn * 48 + tp * 16) * BSTR2 + k16 * 16) * 2 + boff);
                mma_f16(acc[2 * tp],     a, b00, b01);
                mma_f16(acc[2 * tp + 1], a, b10, b11);
            }
        }
    }

    {
        const int grp = lane >> 2;
        const int tig = lane & 3;
        const int rl = wm * 16 + grp;
        const int r0 = rowBase + rl;
        const int tile = blockIdx.x >> 1;
        const float mu0 = g_mu[r0],     rs0 = g_rs[r0];
        const float mu1 = g_mu[r0 + 8], rs1 = g_rs[r0 + 8];
        #pragma unroll
        for (int tn = 0; tn < 6; tn++) {
            const int c = nbase + wn * 48 + tn * 8 + tig * 2;
            const float ws0 = g_wsum[c],   wb0 = g_wbeta[c];
            const float ws1 = g_wsum[c+1], wb1 = g_wbeta[c+1];
            const float v00 = rs0 * (acc[tn][0] - mu0 * ws0) + wb0;
            const float v01 = rs0 * (acc[tn][1] - mu0 * ws1) + wb1;
            const float v10 = rs1 * (acc[tn][2] - mu1 * ws0) + wb0;
            const float v11 = rs1 * (acc[tn][3] - mu1 * ws1) + wb1;
            if (c < 64) {
                __half* dst = g_qh + (size_t)r0 * HEAD + c;
                *(uint32_t*)dst            = pack_h2(v00 * QSC, v01 * QSC);
                *(uint32_t*)(dst + 8*HEAD) = pack_h2(v10 * QSC, v11 * QSC);
            } else if (c < 128) {
                __half* dst = g_kh + (size_t)r0 * HEAD + (c - 64);
                *(uint32_t*)dst            = pack_h2(v00, v01);
                *(uint32_t*)(dst + 8*HEAD) = pack_h2(v10, v11);
            } else {
                const int h = c - 128;
                __half* vt = g_vth + (size_t)tile * 4096;
                vt[(h    ) * 64 + rl    ] = __float2half_rn(v00);
                vt[(h + 1) * 64 + rl    ] = __float2half_rn(v01);
                vt[(h    ) * 64 + rl + 8] = __float2half_rn(v10);
                vt[(h + 1) * 64 + rl + 8] = __float2half_rn(v11);
            }
        }
    }
}

// ================= Kernel 2: attention + fused combine (split-KV x4) =========
// Diagonal tile: warp w only needs key chunks ntp <= w (16-key granularity);
// skipped chunks are fully masked (existing mask code sets them to -1e30, and
// their P is exactly 0, so skipping their PV MMAs is bit-exact).
#define KSTR2 72
#define VSTR2 72
#define K2_STAGE ((64*KSTR2 + 64*VSTR2) * 2)
#define K2_SMEM (3 * K2_STAGE)

__global__ void __launch_bounds__(128, 4)
attn_mma_kernel(float* __restrict__ out)
{
    extern __shared__ char sm2[];
    __shared__ int s_merge;

    const int tid  = threadIdx.x;
    const int warp = tid >> 5;
    const int lane = tid & 31;
    const int grp  = lane >> 2;
    const int tig  = lane & 3;

    const int b  = blockIdx.x >> 7;
    const int qt = 31 - ((blockIdx.x >> 2) & 31);
    const int h  = blockIdx.x & 3;
    const int qbase = qt * 64;
    const int nkv = (qt >= h) ? (((qt - h) >> 2) + 1) : 0;

    float* OM = g_om + ((size_t)h * NROWS + (size_t)b * SEQ + qbase) * HEAD;
    float* M_ = g_m + (size_t)h * NROWS + (size_t)b * SEQ + qbase;
    float* L_ = g_l + (size_t)h * NROWS + (size_t)b * SEQ + qbase;

    const int rl0 = warp * 16 + grp;
    const int rl1 = rl0 + 8;

    if (nkv == 0) {
        float4* om4 = (float4*)OM;
        for (int i = tid; i < 64 * 16; i += 128)
            om4[i] = make_float4(0.f, 0.f, 0.f, 0.f);
        if (tid < 64) { M_[tid] = -1e30f; L_[tid] = 0.f; }
    } else {
        const __half* K  = g_kh  + (size_t)b * SEQ * HEAD;
        const __half* VT = g_vth + (size_t)(b * 32) * 4096;

        const uint32_t k_u = smem_u32(sm2);
        const uint32_t v_u = k_u + 64 * KSTR2 * 2;

        const int mi = lane >> 3, mrow = lane & 7;
        const int koff = (((mi >> 1) * 8 + mrow) * KSTR2 + (mi & 1) * 8) * 2;
        const int voff = (((mi >> 1) * 8 + mrow) * VSTR2 + (mi & 1) * 8) * 2;

        auto stage = [&](int i, int slot) {
            const __half* Kg = K  + (size_t)(h + 4 * i) * 64 * HEAD;
            const __half* Vg = VT + (size_t)(h + 4 * i) * 4096;
            const uint32_t kb = k_u + slot * K2_STAGE;
            const uint32_t vb = v_u + slot * K2_STAGE;
            #pragma unroll
            for (int u = 0; u < 4; u++) {
                const int idx = tid + 128 * u;
                const int row = idx >> 3, c8 = idx & 7;
                CP_ASYNC16(kb + (row * KSTR2 + c8 * 8) * 2, Kg + row * HEAD + c8 * 8);
                CP_ASYNC16(vb + (row * VSTR2 + c8 * 8) * 2, Vg + row * 64 + c8 * 8);
            }
            CP_COMMIT();
        };

        stage(0, 0);
        if (nkv > 1) stage(1, 1);

        uint32_t qa[4][4];
        {
            const __half* Qr0 = g_qh + ((size_t)b * SEQ + qbase + rl0) * HEAD;
            const __half* Qr1 = g_qh + ((size_t)b * SEQ + qbase + rl1) * HEAD;
            #pragma unroll
            for (int kc = 0; kc < 4; kc++) {
                const int kk = kc * 16;
                qa[kc][0] = __ldg((const uint32_t*)(Qr0 + kk + 2 * tig));
                qa[kc][1] = __ldg((const uint32_t*)(Qr1 + kk + 2 * tig));
                qa[kc][2] = __ldg((const uint32_t*)(Qr0 + kk + 8 + 2 * tig));
                qa[kc][3] = __ldg((const uint32_t*)(Qr1 + kk + 8 + 2 * tig));
            }
        }

        float o[8][4];
        #pragma unroll
        for (int nt = 0; nt < 8; nt++)
            #pragma unroll
            for (int j = 0; j < 4; j++) o[nt][j] = 0.f;
        float m0 = -1e30f, m1 = -1e30f, l0 = 0.f, l1 = 0.f;

        for (int i = 0; i < nkv; i++) {
            if (i + 1 < nkv) { CP_WAIT(1); } else { CP_WAIT(0); }
            __syncthreads();
            if (i + 2 < nkv) {
                int slot = i + 2; slot -= (slot / 3) * 3;
                stage(i + 2, slot);
            }

            int cslot = i; cslot -= (cslot / 3) * 3;
            const uint32_t kb_u = k_u + cslot * K2_STAGE;
            const uint32_t vb_u = v_u + cslot * K2_STAGE;
            const int kt = h + 4 * i;
            const bool diag = (kt == qt);
            const int ntpmax = diag ? (warp + 1) : 4;   // live 16-key chunks

            float s[8][4];
            #pragma unroll
            for (int nt = 0; nt < 8; nt++)
                #pragma unroll
                for (int j = 0; j < 4; j++) s[nt][j] = 0.f;

            #pragma unroll
            for (int kc = 0; kc < 4; kc++) {
                #pragma unroll
                for (int ntp = 0; ntp < 4; ntp++) {
                    if (ntp < ntpmax) {
                        uint32_t b00, b01, b10, b11;
                        ldsm_x4(b00, b01, b10, b11,
                                kb_u + (ntp * 16 * KSTR2 + kc * 16) * 2 + koff);
                        mma_f16(s[2 * ntp],     qa[kc], b00, b01);
                        mma_f16(s[2 * ntp + 1], qa[kc], b10, b11);
                    }
                }
            }

            if (diag) {
                #pragma unroll
                for (int nt = 0; nt < 8; nt++) {
                    const int c0 = nt * 8 + 2 * tig;
                    if (c0     > rl0) s[nt][0] = -1e30f;
                    if (c0 + 1 > rl0) s[nt][1] = -1e30f;
                    if (c0     > rl1) s[nt][2] = -1e30f;
                    if (c0 + 1 > rl1) s[nt][3] = -1e30f;
                }
            }

            float mx0 = -1e30f, mx1 = -1e30f;
            #pragma unroll
            for (int nt = 0; nt < 8; nt++) {
                mx0 = fmaxf(mx0, fmaxf(s[nt][0], s[nt][1]));
                mx1 = fmaxf(mx1, fmaxf(s[nt][2], s[nt][3]));
            }
            mx0 = fmaxf(mx0, __shfl_xor_sync(0xffffffffu, mx0, 1));
            mx0 = fmaxf(mx0, __shfl_xor_sync(0xffffffffu, mx0, 2));
            mx1 = fmaxf(mx1, __shfl_xor_sync(0xffffffffu, mx1, 1));
            mx1 = fmaxf(mx1, __shfl_xor_sync(0xffffffffu, mx1, 2));

            const float mn0 = fmaxf(m0, mx0);
            const float mn1 = fmaxf(m1, mx1);
            const float cor0 = ex2(m0 - mn0);
            const float cor1 = ex2(m1 - mn1);
            m0 = mn0; m1 = mn1;

            float sum0 = 0.f, sum1 = 0.f;
            #pragma unroll
            for (int nt = 0; nt < 8; nt++) {
                s[nt][0] = ex2(s[nt][0] - mn0);
                s[nt][1] = ex2(s[nt][1] - mn0);
                s[nt][2] = ex2(s[nt][2] - mn1);
                s[nt][3] = ex2(s[nt][3] - mn1);
                sum0 += s[nt][0] + s[nt][1];
                sum1 += s[nt][2] + s[nt][3];
            }
            sum0 += __shfl_xor_sync(0xffffffffu, sum0, 1);
            sum0 += __shfl_xor_sync(0xffffffffu, sum0, 2);
            sum1 += __shfl_xor_sync(0xffffffffu, sum1, 1);
            sum1 += __shfl_xor_sync(0xffffffffu, sum1, 2);
            l0 = l0 * cor0 + sum0;
            l1 = l1 * cor1 + sum1;

            #pragma unroll
            for (int nt = 0; nt < 8; nt++) {
                o[nt][0] *= cor0; o[nt][1] *= cor0;
                o[nt][2] *= cor1; o[nt][3] *= cor1;
            }

            // O += P V : skip key chunks whose P is exactly zero (masked)
            #pragma unroll
            for (int kc = 0; kc < 4; kc++) {
                if (kc < ntpmax) {
                    uint32_t pa[4];
                    pa[0] = pack_h2(s[2*kc][0],     s[2*kc][1]);
                    pa[1] = pack_h2(s[2*kc][2],     s[2*kc][3]);
                    pa[2] = pack_h2(s[2*kc + 1][0], s[2*kc + 1][1]);
                    pa[3] = pack_h2(s[2*kc + 1][2], s[2*kc + 1][3]);
                    #pragma unroll
                    for (int ntp = 0; ntp < 4; ntp++) {
                        uint32_t b00, b01, b10, b11;
                        ldsm_x4(b00, b01, b10, b11,
                                vb_u + (ntp * 16 * VSTR2 + kc * 16) * 2 + voff);
                        mma_f16(o[2 * ntp],     pa, b00, b01);
                        mma_f16(o[2 * ntp + 1], pa, b10, b11);
                    }
                }
            }
        }

        #pragma unroll
        for (int nt = 0; nt < 8; nt++) {
            const int c = nt * 8 + 2 * tig;
            *(float2*)(OM + (size_t)rl0 * HEAD + c) = make_float2(o[nt][0], o[nt][1]);
            *(float2*)(OM + (size_t)rl1 * HEAD + c) = make_float2(o[nt][2], o[nt][3]);
        }
        if (tig == 0) {
            M_[rl0] = m0; L_[rl0] = l0;
            M_[rl1] = m1; L_[rl1] = l1;
        }
    }

    // ---- fused combine: last of the 4 partial blocks merges (b, qt) ----
    __syncthreads();
    if (tid == 0) {
        __threadfence();
        const int old = atomicAdd(&g_cnt[b * 32 + qt], 1);
        s_merge = (old == SPLITK - 1);
    }
    __syncthreads();

    if (s_merge) {
        const size_t rowb = (size_t)b * SEQ + qbase;
        for (int idx = tid; idx < 64 * 16; idx += 128) {
            const int row = idx >> 4;
            const int c4  = idx & 15;
            const size_t grow = rowb + row;

            float mm[SPLITK], ll[SPLITK];
            float M = -1e30f;
            #pragma unroll
            for (int u = 0; u < SPLITK; u++) {
                mm[u] = g_m[(size_t)u * NROWS + grow];
                ll[u] = g_l[(size_t)u * NROWS + grow];
                M = fmaxf(M, mm[u]);
            }
            float denom = 0.f, aw[SPLITK];
            #pragma unroll
            for (int u = 0; u < SPLITK; u++) {
                aw[u] = ex2(mm[u] - M);
                denom += ll[u] * aw[u];
            }
            const float inv = 1.0f / denom;

            float4 r = make_float4(0.f, 0.f, 0.f, 0.f);
            #pragma unroll
            for (int u = 0; u < SPLITK; u++) {
                const float w = aw[u] * inv;
                const float4 oh = *(const float4*)(g_om + ((size_t)u * NROWS + grow) * HEAD + c4 * 4);
                r.x += oh.x * w; r.y += oh.y * w;
                r.z += oh.z * w; r.w += oh.w * w;
            }
            *(float4*)(out + grow * HEAD + c4 * 4) = r;
        }
        if (tid == 0) g_cnt[b * 32 + qt] = 0;
    }
}

// ================= launch =================
extern "C" void kernel_launch(void* const* d_in, const int* in_sizes, int n_in,
                              void* d_out, int out_size)
{
    const float* x     = (const float*)d_in[0];
    const float* gamma = (const float*)d_in[1];
    const float* beta  = (const float*)d_in[2];
    const float* Wq    = (const float*)d_in[3];
    const float* Wk    = (const float*)d_in[4];
    const float* Wv    = (const float*)d_in[5];
    float* out = (float*)d_out;

    cudaFuncSetAttribute(qkv_gemm_kernel, cudaFuncAttributeMaxDynamicSharedMemorySize, (int)K1_SMEM);
    cudaFuncSetAttribute(attn_mma_kernel, cudaFuncAttributeMaxDynamicSharedMemorySize, (int)K2_SMEM);

    prep_kernel<<<NROWS / 8 + 192, 256>>>(x, gamma, beta, Wq, Wk, Wv);
    qkv_gemm_kernel<<<(NROWS / 64) * 2, 256, K1_SMEM>>>();
    attn_mma_kernel<<<BATCH * 32 * SPLITK, 128, K2_SMEM>>>(out);
}

// round 15
// speedup vs baseline: 1.0530x; 1.0530x over previous
#include <cuda_runtime.h>
#include <cuda_fp16.h>
#include <stdint.h>
#include <math.h>

// Problem constants
#define BATCH 4
#define SEQ   2048
#define EMB   1024
#define HEAD  64
#define NROWS (BATCH * SEQ)   // 8192
#define SPLITK 4
#define QSC   0.180336881f    // (1/8) * log2(e) : softmax in exp2 domain

// ---------------- scratch ----------------
__device__ __half g_xh[NROWS * EMB];           // fp16-rounded x
__device__ __half g_qh[NROWS * HEAD];          // fp16, pre-scaled by QSC
__device__ __half g_kh[NROWS * HEAD];          // fp16
__device__ __half g_vth[NROWS * HEAD];         // fp16, per-64-tile transposed [tile][head][key]
__device__ float  g_om[SPLITK * NROWS * HEAD];
__device__ float  g_m [SPLITK * NROWS];        // log2-domain row maxima
__device__ float  g_l [SPLITK * NROWS];
__device__ float  g_mu[NROWS];
__device__ float  g_rs[NROWS];
__device__ __half g_wh[192 * EMB];
__device__ float  g_wsum [192];
__device__ float  g_wbeta[192];
__device__ int    g_cnt[BATCH * 32];

__device__ __forceinline__ uint32_t pack_h2(float lo, float hi) {
    __half2 h = __floats2half2_rn(lo, hi);
    return *reinterpret_cast<uint32_t*>(&h);
}

__device__ __forceinline__ float ex2(float x) {
    float r;
    asm("ex2.approx.ftz.f32 %0, %1;" : "=f"(r) : "f"(x));
    return r;
}

__device__ __forceinline__ void mma_f16(float* d, const uint32_t* a,
                                        uint32_t b0, uint32_t b1) {
    asm volatile(
        "mma.sync.aligned.m16n8k16.row.col.f32.f16.f16.f32 "
        "{%0,%1,%2,%3}, {%4,%5,%6,%7}, {%8,%9}, {%0,%1,%2,%3};"
        : "+f"(d[0]), "+f"(d[1]), "+f"(d[2]), "+f"(d[3])
        : "r"(a[0]), "r"(a[1]), "r"(a[2]), "r"(a[3]), "r"(b0), "r"(b1));
}

__device__ __forceinline__ void ldsm_x4(uint32_t& r0, uint32_t& r1,
                                        uint32_t& r2, uint32_t& r3, uint32_t addr) {
    asm volatile("ldmatrix.sync.aligned.m8n8.x4.shared.b16 {%0,%1,%2,%3}, [%4];"
                 : "=r"(r0), "=r"(r1), "=r"(r2), "=r"(r3) : "r"(addr));
}

__device__ __forceinline__ uint32_t smem_u32(const void* p) {
    return (uint32_t)__cvta_generic_to_shared(p);
}

#define CP_ASYNC16(dst_u32, src_ptr) \
    asm volatile("cp.async.cg.shared.global [%0], [%1], 16;" \
                 :: "r"(dst_u32), "l"(src_ptr))
#define CP_COMMIT() asm volatile("cp.async.commit_group;")
#define CP_WAIT(N)  asm volatile("cp.async.wait_group %0;" :: "n"(N))

// ================= Kernel 0: prep (x->fp16 + LN stats + weight prep) =========
__global__ void __launch_bounds__(256)
prep_kernel(const float* __restrict__ x,
            const float* __restrict__ gamma,
            const float* __restrict__ beta,
            const float* __restrict__ Wq,
            const float* __restrict__ Wk,
            const float* __restrict__ Wv)
{
    const int tid  = threadIdx.x;
    const int warp = tid >> 5;
    const int lane = tid & 31;

    if (blockIdx.x < NROWS / 8) {
        const int r = blockIdx.x * 8 + warp;
        const float4* xr = (const float4*)(x + (size_t)r * EMB);
        __half* xh = g_xh + (size_t)r * EMB;
        float sum = 0.f, sq = 0.f;
        #pragma unroll
        for (int t = 0; t < 8; t++) {
            const int i4 = lane + 32 * t;
            float4 v = xr[i4];
            const float f0 = __half2float(__float2half_rn(v.x));
            const float f1 = __half2float(__float2half_rn(v.y));
            const float f2 = __half2float(__float2half_rn(v.z));
            const float f3 = __half2float(__float2half_rn(v.w));
            uint2 st;
            st.x = pack_h2(f0, f1);
            st.y = pack_h2(f2, f3);
            *reinterpret_cast<uint2*>(xh + i4 * 4) = st;
            sum += f0 + f1 + f2 + f3;
            sq  += f0*f0 + f1*f1 + f2*f2 + f3*f3;
        }
        #pragma unroll
        for (int off = 16; off; off >>= 1) {
            sum += __shfl_xor_sync(0xffffffffu, sum, off);
            sq  += __shfl_xor_sync(0xffffffffu, sq,  off);
        }
        if (lane == 0) {
            const float inv = 1.0f / (float)EMB;
            const float mu = sum * inv;
            const float var = sq * inv - mu * mu;
            g_mu[r] = mu;
            g_rs[r] = rsqrtf(var + 1e-5f);
        }
    } else {
        __shared__ float red[16];
        const int c = blockIdx.x - NROWS / 8;
        const float* Wr = (c < 64)  ? (Wq + (size_t)c * EMB)
                        : (c < 128) ? (Wk + (size_t)(c - 64) * EMB)
                                    : (Wv + (size_t)(c - 128) * EMB);
        float s_w = 0.f, s_b = 0.f;
        {
            float4 w = *(const float4*)(Wr + tid * 4);
            float4 g = *(const float4*)(gamma + tid * 4);
            float4 b = *(const float4*)(beta  + tid * 4);
            __half h0 = __float2half_rn(w.x * g.x);
            __half h1 = __float2half_rn(w.y * g.y);
            __half h2 = __float2half_rn(w.z * g.z);
            __half h3 = __float2half_rn(w.w * g.w);
            __half2 p0 = __halves2half2(h0, h1);
            __half2 p1 = __halves2half2(h2, h3);
            uint2 st;
            st.x = *reinterpret_cast<uint32_t*>(&p0);
            st.y = *reinterpret_cast<uint32_t*>(&p1);
            *reinterpret_cast<uint2*>(g_wh + (size_t)c * EMB + tid * 4) = st;
            s_w += __half2float(h0) + __half2float(h1) + __half2float(h2) + __half2float(h3);
            s_b += w.x*b.x + w.y*b.y + w.z*b.z + w.w*b.w;
        }
        #pragma unroll
        for (int off = 16; off; off >>= 1) {
            s_w += __shfl_xor_sync(0xffffffffu, s_w, off);
            s_b += __shfl_xor_sync(0xffffffffu, s_b, off);
        }
        if (lane == 0) { red[warp] = s_w; red[warp + 8] = s_b; }
        __syncthreads();
        if (tid == 0) {
            float aw = 0.f, ab = 0.f;
            #pragma unroll
            for (int i = 0; i < 8; i++) { aw += red[i]; ab += red[i + 8]; }
            g_wsum[c] = aw; g_wbeta[c] = ab;
        }
    }
}

// ================= Kernel 1: QKV GEMM (M=128 x N=96, fp16 + ldmatrix, 3-stage)
// Warp grid 4m x 2n; warp tile 32x48. Halves B staging traffic vs M=64.
#define K1_KC 64
#define ASTR2 72
#define BSTR2 72
#define K1_STAGE ((128*ASTR2 + 96*BSTR2) * 2)
#define K1_SMEM (3 * K1_STAGE)

__global__ void __launch_bounds__(256, 2)
qkv_gemm_kernel()
{
    extern __shared__ char sm1[];

    const int tid  = threadIdx.x;
    const int warp = tid >> 5;
    const int lane = tid & 31;
    const int rowBase = (blockIdx.x >> 1) * 128;
    const int nbase   = (blockIdx.x & 1) * 96;

    const uint32_t a_u = smem_u32(sm1);                       // A: [stage][128][72]
    const uint32_t b_u = a_u + 128 * ASTR2 * 2;               // B: [stage][96][72]

    const int wm  = warp >> 1;   // 0..3
    const int wn  = warp & 1;    // 0..1

    const int mi = lane >> 3, mrow = lane & 7;
    const int aoff = ((wm * 32 + (mi & 1) * 8 + mrow) * ASTR2 + (mi >> 1) * 8) * 2;
    const int boff = (((mi >> 1) * 8 + mrow) * BSTR2 + (mi & 1) * 8) * 2;

    auto stage = [&](int ch, int slot) {
        const int k0 = ch * K1_KC;
        const uint32_t au = a_u + slot * K1_STAGE;
        const uint32_t bu = b_u + slot * K1_STAGE;
        #pragma unroll
        for (int i = 0; i < 4; i++) {
            const int idx = tid + 256 * i;          // 0..1023
            const int row = idx >> 3, c8 = idx & 7;
            CP_ASYNC16(au + (row * ASTR2 + c8 * 8) * 2,
                       g_xh + (size_t)(rowBase + row) * EMB + k0 + c8 * 8);
        }
        #pragma unroll
        for (int i = 0; i < 3; i++) {
            const int idx = tid + 256 * i;          // 0..767
            const int c = idx >> 3, c8 = idx & 7;
            CP_ASYNC16(bu + (c * BSTR2 + c8 * 8) * 2,
                       g_wh + (size_t)(nbase + c) * EMB + k0 + c8 * 8);
        }
        CP_COMMIT();
    };

    stage(0, 0);
    stage(1, 1);

    float acc[2][6][4];
    #pragma unroll
    for (int tm = 0; tm < 2; tm++)
        #pragma unroll
        for (int i = 0; i < 6; i++)
            #pragma unroll
            for (int j = 0; j < 4; j++) acc[tm][i][j] = 0.f;

    for (int ch = 0; ch < EMB / K1_KC; ch++) {
        if (ch + 1 < EMB / K1_KC) { CP_WAIT(1); } else { CP_WAIT(0); }
        __syncthreads();
        if (ch + 2 < EMB / K1_KC) {
            int slot = ch + 2; slot -= (slot / 3) * 3;
            stage(ch + 2, slot);
        }

        int cslot = ch; cslot -= (cslot / 3) * 3;
        const uint32_t Ab_u = a_u + cslot * K1_STAGE;
        const uint32_t Bb_u = b_u + cslot * K1_STAGE;

        #pragma unroll
        for (int k16 = 0; k16 < 4; k16++) {
            uint32_t a[2][4];
            ldsm_x4(a[0][0], a[0][1], a[0][2], a[0][3],
                    Ab_u + (k16 * 16) * 2 + aoff);
            ldsm_x4(a[1][0], a[1][1], a[1][2], a[1][3],
                    Ab_u + (16 * ASTR2 + k16 * 16) * 2 + aoff);
            #pragma unroll
            for (int tp = 0; tp < 3; tp++) {
                uint32_t b00, b01, b10, b11;
                ldsm_x4(b00, b01, b10, b11,
                        Bb_u + ((wn * 48 + tp * 16) * BSTR2 + k16 * 16) * 2 + boff);
                mma_f16(acc[0][2 * tp],     a[0], b00, b01);
                mma_f16(acc[0][2 * tp + 1], a[0], b10, b11);
                mma_f16(acc[1][2 * tp],     a[1], b00, b01);
                mma_f16(acc[1][2 * tp + 1], a[1], b10, b11);
            }
        }
    }

    // epilogue: out = rs*(acc - mu*wsum) + wbeta; q scaled QSC; v transposed
    {
        const int grp = lane >> 2;
        const int tig = lane & 3;
        #pragma unroll
        for (int tm = 0; tm < 2; tm++) {
            const int r0 = rowBase + wm * 32 + tm * 16 + grp;
            const float mu0 = g_mu[r0],     rs0 = g_rs[r0];
            const float mu1 = g_mu[r0 + 8], rs1 = g_rs[r0 + 8];
            const int tile = r0 >> 6;
            const int rl64 = r0 & 63;
            #pragma unroll
            for (int tn = 0; tn < 6; tn++) {
                const int c = nbase + wn * 48 + tn * 8 + tig * 2;
                const float ws0 = g_wsum[c],   wb0 = g_wbeta[c];
                const float ws1 = g_wsum[c+1], wb1 = g_wbeta[c+1];
                const float v00 = rs0 * (acc[tm][tn][0] - mu0 * ws0) + wb0;
                const float v01 = rs0 * (acc[tm][tn][1] - mu0 * ws1) + wb1;
                const float v10 = rs1 * (acc[tm][tn][2] - mu1 * ws0) + wb0;
                const float v11 = rs1 * (acc[tm][tn][3] - mu1 * ws1) + wb1;
                if (c < 64) {
                    __half* dst = g_qh + (size_t)r0 * HEAD + c;
                    *(uint32_t*)dst            = pack_h2(v00 * QSC, v01 * QSC);
                    *(uint32_t*)(dst + 8*HEAD) = pack_h2(v10 * QSC, v11 * QSC);
                } else if (c < 128) {
                    __half* dst = g_kh + (size_t)r0 * HEAD + (c - 64);
                    *(uint32_t*)dst            = pack_h2(v00, v01);
                    *(uint32_t*)(dst + 8*HEAD) = pack_h2(v10, v11);
                } else {
                    const int hh = c - 128;
                    __half* vt = g_vth + (size_t)tile * 4096;
                    vt[(hh    ) * 64 + rl64    ] = __float2half_rn(v00);
                    vt[(hh + 1) * 64 + rl64    ] = __float2half_rn(v01);
                    vt[(hh    ) * 64 + rl64 + 8] = __float2half_rn(v10);
                    vt[(hh + 1) * 64 + rl64 + 8] = __float2half_rn(v11);
                }
            }
        }
    }
}

// ================= Kernel 2: attention + fused combine (split-KV x4) =========
// (R12 mainloop — branch-free; measured best)
#define KSTR2 72
#define VSTR2 72
#define K2_STAGE ((64*KSTR2 + 64*VSTR2) * 2)
#define K2_SMEM (3 * K2_STAGE)

__global__ void __launch_bounds__(128, 4)
attn_mma_kernel(float* __restrict__ out)
{
    extern __shared__ char sm2[];
    __shared__ int s_merge;

    const int tid  = threadIdx.x;
    const int warp = tid >> 5;
    const int lane = tid & 31;
    const int grp  = lane >> 2;
    const int tig  = lane & 3;

    const int b  = blockIdx.x >> 7;
    const int qt = 31 - ((blockIdx.x >> 2) & 31);
    const int h  = blockIdx.x & 3;
    const int qbase = qt * 64;
    const int nkv = (qt >= h) ? (((qt - h) >> 2) + 1) : 0;

    float* OM = g_om + ((size_t)h * NROWS + (size_t)b * SEQ + qbase) * HEAD;
    float* M_ = g_m + (size_t)h * NROWS + (size_t)b * SEQ + qbase;
    float* L_ = g_l + (size_t)h * NROWS + (size_t)b * SEQ + qbase;

    const int rl0 = warp * 16 + grp;
    const int rl1 = rl0 + 8;

    if (nkv == 0) {
        float4* om4 = (float4*)OM;
        for (int i = tid; i < 64 * 16; i += 128)
            om4[i] = make_float4(0.f, 0.f, 0.f, 0.f);
        if (tid < 64) { M_[tid] = -1e30f; L_[tid] = 0.f; }
    } else {
        const __half* K  = g_kh  + (size_t)b * SEQ * HEAD;
        const __half* VT = g_vth + (size_t)(b * 32) * 4096;

        const uint32_t k_u = smem_u32(sm2);
        const uint32_t v_u = k_u + 64 * KSTR2 * 2;

        const int mi = lane >> 3, mrow = lane & 7;
        const int koff = (((mi >> 1) * 8 + mrow) * KSTR2 + (mi & 1) * 8) * 2;
        const int voff = (((mi >> 1) * 8 + mrow) * VSTR2 + (mi & 1) * 8) * 2;

        auto stage = [&](int i, int slot) {
            const __half* Kg = K  + (size_t)(h + 4 * i) * 64 * HEAD;
            const __half* Vg = VT + (size_t)(h + 4 * i) * 4096;
            const uint32_t kb = k_u + slot * K2_STAGE;
            const uint32_t vb = v_u + slot * K2_STAGE;
            #pragma unroll
            for (int u = 0; u < 4; u++) {
                const int idx = tid + 128 * u;
                const int row = idx >> 3, c8 = idx & 7;
                CP_ASYNC16(kb + (row * KSTR2 + c8 * 8) * 2, Kg + row * HEAD + c8 * 8);
                CP_ASYNC16(vb + (row * VSTR2 + c8 * 8) * 2, Vg + row * 64 + c8 * 8);
            }
            CP_COMMIT();
        };

        stage(0, 0);
        if (nkv > 1) stage(1, 1);

        uint32_t qa[4][4];
        {
            const __half* Qr0 = g_qh + ((size_t)b * SEQ + qbase + rl0) * HEAD;
            const __half* Qr1 = g_qh + ((size_t)b * SEQ + qbase + rl1) * HEAD;
            #pragma unroll
            for (int kc = 0; kc < 4; kc++) {
                const int kk = kc * 16;
                qa[kc][0] = __ldg((const uint32_t*)(Qr0 + kk + 2 * tig));
                qa[kc][1] = __ldg((const uint32_t*)(Qr1 + kk + 2 * tig));
                qa[kc][2] = __ldg((const uint32_t*)(Qr0 + kk + 8 + 2 * tig));
                qa[kc][3] = __ldg((const uint32_t*)(Qr1 + kk + 8 + 2 * tig));
            }
        }

        float o[8][4];
        #pragma unroll
        for (int nt = 0; nt < 8; nt++)
            #pragma unroll
            for (int j = 0; j < 4; j++) o[nt][j] = 0.f;
        float m0 = -1e30f, m1 = -1e30f, l0 = 0.f, l1 = 0.f;

        for (int i = 0; i < nkv; i++) {
            if (i + 1 < nkv) { CP_WAIT(1); } else { CP_WAIT(0); }
            __syncthreads();
            if (i + 2 < nkv) {
                int slot = i + 2; slot -= (slot / 3) * 3;
                stage(i + 2, slot);
            }

            int cslot = i; cslot -= (cslot / 3) * 3;
            const uint32_t kb_u = k_u + cslot * K2_STAGE;
            const uint32_t vb_u = v_u + cslot * K2_STAGE;
            const int kt = h + 4 * i;

            float s[8][4];
            #pragma unroll
            for (int nt = 0; nt < 8; nt++)
                #pragma unroll
                for (int j = 0; j < 4; j++) s[nt][j] = 0.f;

            #pragma unroll
            for (int kc = 0; kc < 4; kc++) {
                #pragma unroll
                for (int ntp = 0; ntp < 4; ntp++) {
                    uint32_t b00, b01, b10, b11;
                    ldsm_x4(b00, b01, b10, b11,
                            kb_u + (ntp * 16 * KSTR2 + kc * 16) * 2 + koff);
                    mma_f16(s[2 * ntp],     qa[kc], b00, b01);
                    mma_f16(s[2 * ntp + 1], qa[kc], b10, b11);
                }
            }

            if (kt == qt) {
                #pragma unroll
                for (int nt = 0; nt < 8; nt++) {
                    const int c0 = nt * 8 + 2 * tig;
                    if (c0     > rl0) s[nt][0] = -1e30f;
                    if (c0 + 1 > rl0) s[nt][1] = -1e30f;
                    if (c0     > rl1) s[nt][2] = -1e30f;
                    if (c0 + 1 > rl1) s[nt][3] = -1e30f;
                }
            }

            float mx0 = -1e30f, mx1 = -1e30f;
            #pragma unroll
            for (int nt = 0; nt < 8; nt++) {
                mx0 = fmaxf(mx0, fmaxf(s[nt][0], s[nt][1]));
                mx1 = fmaxf(mx1, fmaxf(s[nt][2], s[nt][3]));
            }
            mx0 = fmaxf(mx0, __shfl_xor_sync(0xffffffffu, mx0, 1));
            mx0 = fmaxf(mx0, __shfl_xor_sync(0xffffffffu, mx0, 2));
            mx1 = fmaxf(mx1, __shfl_xor_sync(0xffffffffu, mx1, 1));
            mx1 = fmaxf(mx1, __shfl_xor_sync(0xffffffffu, mx1, 2));

            const float mn0 = fmaxf(m0, mx0);
            const float mn1 = fmaxf(m1, mx1);
            const float cor0 = ex2(m0 - mn0);
            const float cor1 = ex2(m1 - mn1);
            m0 = mn0; m1 = mn1;

            float sum0 = 0.f, sum1 = 0.f;
            #pragma unroll
            for (int nt = 0; nt < 8; nt++) {
                s[nt][0] = ex2(s[nt][0] - mn0);
                s[nt][1] = ex2(s[nt][1] - mn0);
                s[nt][2] = ex2(s[nt][2] - mn1);
                s[nt][3] = ex2(s[nt][3] - mn1);
                sum0 += s[nt][0] + s[nt][1];
                sum1 += s[nt][2] + s[nt][3];
            }
            sum0 += __shfl_xor_sync(0xffffffffu, sum0, 1);
            sum0 += __shfl_xor_sync(0xffffffffu, sum0, 2);
            sum1 += __shfl_xor_sync(0xffffffffu, sum1, 1);
            sum1 += __shfl_xor_sync(0xffffffffu, sum1, 2);
            l0 = l0 * cor0 + sum0;
            l1 = l1 * cor1 + sum1;

            #pragma unroll
            for (int nt = 0; nt < 8; nt++) {
                o[nt][0] *= cor0; o[nt][1] *= cor0;
                o[nt][2] *= cor1; o[nt][3] *= cor1;
            }

            #pragma unroll
            for (int kc = 0; kc < 4; kc++) {
                uint32_t pa[4];
                pa[0] = pack_h2(s[2*kc][0],     s[2*kc][1]);
                pa[1] = pack_h2(s[2*kc][2],     s[2*kc][3]);
                pa[2] = pack_h2(s[2*kc + 1][0], s[2*kc + 1][1]);
                pa[3] = pack_h2(s[2*kc + 1][2], s[2*kc + 1][3]);
                #pragma unroll
                for (int ntp = 0; ntp < 4; ntp++) {
                    uint32_t b00, b01, b10, b11;
                    ldsm_x4(b00, b01, b10, b11,
                            vb_u + (ntp * 16 * VSTR2 + kc * 16) * 2 + voff);
                    mma_f16(o[2 * ntp],     pa, b00, b01);
                    mma_f16(o[2 * ntp + 1], pa, b10, b11);
                }
            }
        }

        #pragma unroll
        for (int nt = 0; nt < 8; nt++) {
            const int c = nt * 8 + 2 * tig;
            *(float2*)(OM + (size_t)rl0 * HEAD + c) = make_float2(o[nt][0], o[nt][1]);
            *(float2*)(OM + (size_t)rl1 * HEAD + c) = make_float2(o[nt][2], o[nt][3]);
        }
        if (tig == 0) {
            M_[rl0] = m0; L_[rl0] = l0;
            M_[rl1] = m1; L_[rl1] = l1;
        }
    }

    // ---- fused combine: last of the 4 partial blocks merges (b, qt) ----
    __syncthreads();
    if (tid == 0) {
        __threadfence();
        const int old = atomicAdd(&g_cnt[b * 32 + qt], 1);
        s_merge = (old == SPLITK - 1);
    }
    __syncthreads();

    if (s_merge) {
        const size_t rowb = (size_t)b * SEQ + qbase;
        for (int idx = tid; idx < 64 * 16; idx += 128) {
            const int row = idx >> 4;
            const int c4  = idx & 15;
            const size_t grow = rowb + row;

            float mm[SPLITK], ll[SPLITK];
            float M = -1e30f;
            #pragma unroll
            for (int u = 0; u < SPLITK; u++) {
                mm[u] = g_m[(size_t)u * NROWS + grow];
                ll[u] = g_l[(size_t)u * NROWS + grow];
                M = fmaxf(M, mm[u]);
            }
            float denom = 0.f, aw[SPLITK];
            #pragma unroll
            for (int u = 0; u < SPLITK; u++) {
                aw[u] = ex2(mm[u] - M);
                denom += ll[u] * aw[u];
            }
            const float inv = 1.0f / denom;

            float4 r = make_float4(0.f, 0.f, 0.f, 0.f);
            #pragma unroll
            for (int u = 0; u < SPLITK; u++) {
                const float w = aw[u] * inv;
                const float4 oh = *(const float4*)(g_om + ((size_t)u * NROWS + grow) * HEAD + c4 * 4);
                r.x += oh.x * w; r.y += oh.y * w;
                r.z += oh.z * w; r.w += oh.w * w;
            }
            *(float4*)(out + grow * HEAD + c4 * 4) = r;
        }
        if (tid == 0) g_cnt[b * 32 + qt] = 0;
    }
}

// ================= launch =================
extern "C" void kernel_launch(void* const* d_in, const int* in_sizes, int n_in,
                              void* d_out, int out_size)
{
    const float* x     = (const float*)d_in[0];
    const float* gamma = (const float*)d_in[1];
    const float* beta  = (const float*)d_in[2];
    const float* Wq    = (const float*)d_in[3];
    const float* Wk    = (const float*)d_in[4];
    const float* Wv    = (const float*)d_in[5];
    float* out = (float*)d_out;

    cudaFuncSetAttribute(qkv_gemm_kernel, cudaFuncAttributeMaxDynamicSharedMemorySize, (int)K1_SMEM);
    cudaFuncSetAttribute(attn_mma_kernel, cudaFuncAttributeMaxDynamicSharedMemorySize, (int)K2_SMEM);

    prep_kernel<<<NROWS / 8 + 192, 256>>>(x, gamma, beta, Wq, Wk, Wv);
    qkv_gemm_kernel<<<(NROWS / 128) * 2, 256, K1_SMEM>>>();
    attn_mma_kernel<<<BATCH * 32 * SPLITK, 128, K2_SMEM>>>(out);
}